// round 3
// baseline (speedup 1.0000x reference)
#include <cuda_runtime.h>

#define HH 256
#define WW 256
#define BATCH 8
#define HW 65536

// Scratch (allocation-free rule: __device__ globals)
__device__ float g_x[BATCH * 16 * HW];          // in_conv output  (33.5 MB)
__device__ float g_xs[4 * BATCH * 16 * HW];     // dwconv outputs  (134 MB)

// ---------------------------------------------------------------------------
// K1: 1x1 in_conv 64 -> 16, float4 vectorized (4 px / thread)
// ---------------------------------------------------------------------------
__global__ __launch_bounds__(256) void k_inconv(const float4* __restrict__ cen4,
                                                const float* __restrict__ w,
                                                const float* __restrict__ bias) {
    __shared__ float sw[1024];
    __shared__ float sb[16];
    for (int i = threadIdx.x; i < 1024; i += 256) sw[i] = w[i];
    if (threadIdx.x < 16) sb[threadIdx.x] = bias[threadIdx.x];
    __syncthreads();

    int idx = blockIdx.x * 256 + threadIdx.x;   // 0 .. 131071 (b, p4)
    int b = idx >> 14;
    int p4 = idx & 16383;
    const float4* cp = cen4 + (size_t)(b * 64) * 16384 + p4;

    float4 acc[16];
#pragma unroll
    for (int o = 0; o < 16; o++) { float v = sb[o]; acc[o] = make_float4(v, v, v, v); }

#pragma unroll 4
    for (int i = 0; i < 64; i++) {
        float4 v = __ldg(cp + (size_t)i * 16384);
#pragma unroll
        for (int o = 0; o < 16; o++) {
            float wv = sw[o * 64 + i];
            acc[o].x = fmaf(v.x, wv, acc[o].x);
            acc[o].y = fmaf(v.y, wv, acc[o].y);
            acc[o].z = fmaf(v.z, wv, acc[o].z);
            acc[o].w = fmaf(v.w, wv, acc[o].w);
        }
    }
    float4* xp = reinterpret_cast<float4*>(g_x) + (size_t)(b * 16) * 16384 + p4;
#pragma unroll
    for (int o = 0; o < 16; o++) xp[(size_t)o * 16384] = acc[o];
}

// ---------------------------------------------------------------------------
// K2: all 4 depthwise convs (s = 1,3,5,7), tile 32x16, 2 px per thread
// ---------------------------------------------------------------------------
template <int S>
__device__ __forceinline__ void dw2(const float* __restrict__ sx, int ty, int c0,
                                    const float* __restrict__ wk, float bias,
                                    float& o0, float& o1) {
    constexpr int P = S / 2;
    float a0 = bias, a1 = bias;
#pragma unroll
    for (int kh = 0; kh < S; kh++) {
        const float* row = sx + (ty + 3 - P + kh) * 39 + (c0 + 3 - P);
        float v[S + 1];
#pragma unroll
        for (int j = 0; j <= S; j++) v[j] = row[j];
#pragma unroll
        for (int kw = 0; kw < S; kw++) {
            float wv = wk[kh * S + kw];
            a0 = fmaf(wv, v[kw], a0);
            a1 = fmaf(wv, v[kw + 1], a1);
        }
    }
    o0 = a0; o1 = a1;
}

__global__ __launch_bounds__(256) void k_dw(
    const float* __restrict__ w1, const float* __restrict__ b1,
    const float* __restrict__ w3, const float* __restrict__ b3,
    const float* __restrict__ w5, const float* __restrict__ b5,
    const float* __restrict__ w7, const float* __restrict__ b7) {
    __shared__ float sdw[16 * 84];   // per channel: [w1(1), w3(9), w5(25), w7(49)]
    __shared__ float sdb[64];        // [c][branch]
    __shared__ float sxt[22 * 39];   // one channel tile + halo 3 (stride 39)

    int tid = threadIdx.x;
    for (int i = tid; i < 16;  i += 256) sdw[i * 84] = w1[i];
    for (int i = tid; i < 144; i += 256) sdw[(i / 9)  * 84 + 1  + (i % 9)]  = w3[i];
    for (int i = tid; i < 400; i += 256) sdw[(i / 25) * 84 + 10 + (i % 25)] = w5[i];
    for (int i = tid; i < 784; i += 256) sdw[(i / 49) * 84 + 35 + (i % 49)] = w7[i];
    if (tid < 16) {
        sdb[tid * 4 + 0] = b1[tid]; sdb[tid * 4 + 1] = b3[tid];
        sdb[tid * 4 + 2] = b5[tid]; sdb[tid * 4 + 3] = b7[tid];
    }

    int ty = tid >> 4;          // 0..15
    int c0 = (tid & 15) * 2;    // tile-local col (even)
    int y0 = blockIdx.y * 16, x0 = blockIdx.x * 32;
    int b = blockIdx.z;
    int h = y0 + ty, wc0 = x0 + c0;

#pragma unroll 1
    for (int c = 0; c < 16; c++) {
        __syncthreads();
        const float* src = g_x + (size_t)(b * 16 + c) * HW;
        for (int i = tid; i < 22 * 38; i += 256) {
            int r = i / 38, cl = i % 38;
            int gy = y0 - 3 + r, gx = x0 - 3 + cl;
            float v = 0.f;
            if ((unsigned)gy < 256u && (unsigned)gx < 256u)
                v = __ldg(src + gy * 256 + gx);
            sxt[r * 39 + cl] = v;
        }
        __syncthreads();

        const float* wcp = sdw + c * 84;
        size_t pix = (size_t)h * 256 + wc0;
        float o0, o1;
        dw2<1>(sxt, ty, c0, wcp + 0,  sdb[c * 4 + 0], o0, o1);
        *reinterpret_cast<float2*>(g_xs + (size_t)((0 * BATCH + b) * 16 + c) * HW + pix) = make_float2(o0, o1);
        dw2<3>(sxt, ty, c0, wcp + 1,  sdb[c * 4 + 1], o0, o1);
        *reinterpret_cast<float2*>(g_xs + (size_t)((1 * BATCH + b) * 16 + c) * HW + pix) = make_float2(o0, o1);
        dw2<5>(sxt, ty, c0, wcp + 10, sdb[c * 4 + 2], o0, o1);
        *reinterpret_cast<float2*>(g_xs + (size_t)((2 * BATCH + b) * 16 + c) * HW + pix) = make_float2(o0, o1);
        dw2<7>(sxt, ty, c0, wcp + 35, sdb[c * 4 + 3], o0, o1);
        *reinterpret_cast<float2*>(g_xs + (size_t)((3 * BATCH + b) * 16 + c) * HW + pix) = make_float2(o0, o1);
    }
}

// ---------------------------------------------------------------------------
// K3: fused shifts + grouped mixes + sort8 + branch contraction + sort4 +
//     base conv + SiLU + final 1x1 + sigmoid.   Tile 32x16, 512 threads.
// ---------------------------------------------------------------------------
__device__ __forceinline__ void ce(float& a, float& b) {
    float lo = fminf(a, b);
    float hi = fmaxf(a, b);
    a = lo; b = hi;
}

template <int S, int C>
__device__ __forceinline__ float branch_val(const float* __restrict__ sx, int ty,
                                            int tx, const float* __restrict__ wB) {
    const float* ctr = sx + (ty + S) * C + (tx + S);
    float xc = ctr[0];
    float T[8];
    T[0] = xc - ctr[-S * C - S];
    T[1] = xc - ctr[-S * C];
    T[2] = xc - ctr[-S * C + S];
    T[3] = xc - ctr[S];
    T[4] = xc - ctr[S * C + S];
    T[5] = xc - ctr[S * C];
    T[6] = xc - ctr[S * C - S];
    T[7] = xc - ctr[-S];
    float Sv[4];
#pragma unroll
    for (int k = 0; k < 4; k++) Sv[k] = T[k] + T[k + 4];

    float w10 = wB[0], w11 = wB[1], w12 = wB[2], w13x2 = wB[3], b1 = wB[4];
    // o_k and o_{k+4} share the S-terms -> 4 shared bases
    float base[4];
#pragma unroll
    for (int j = 0; j < 4; j++) {
        float o = fmaf(w10, Sv[(j + 1) & 3], b1);
        o = fmaf(w11, Sv[(j + 3) & 3], o);
        base[j] = fmaf(w12, Sv[(j + 2) & 3], o);
    }
    float v[8];
#pragma unroll
    for (int k = 0; k < 8; k++)
        v[k] = fmaf(w13x2, T[(k + 4) & 7], base[k & 3]) * T[k];  // wB[3] pre-doubled

    // Batcher odd-even mergesort, 8 elems, 19 CEs, ascending
    ce(v[0], v[1]); ce(v[2], v[3]); ce(v[0], v[2]); ce(v[1], v[3]); ce(v[1], v[2]);
    ce(v[4], v[5]); ce(v[6], v[7]); ce(v[4], v[6]); ce(v[5], v[7]); ce(v[5], v[6]);
    ce(v[0], v[4]); ce(v[1], v[5]); ce(v[2], v[6]); ce(v[3], v[7]);
    ce(v[2], v[4]); ce(v[3], v[5]);
    ce(v[1], v[2]); ce(v[3], v[4]); ce(v[5], v[6]);

    float r = wB[13];
#pragma unroll
    for (int j = 0; j < 8; j++) r = fmaf(v[j], wB[5 + j], r);
    return r;
}

template <int S>
__device__ __forceinline__ void load_region(float* __restrict__ dst,
                                            const float* __restrict__ src,
                                            int y0, int x0, int tid) {
    constexpr int R = 16 + 2 * S, C = 32 + 2 * S;
#pragma unroll 1
    for (int i = tid; i < R * C; i += 512) {
        int r = i / C, cl = i % C;
        int gy = y0 - S + r, gx = x0 - S + cl;
        float v = 0.f;
        if ((unsigned)gy < 256u && (unsigned)gx < 256u)
            v = __ldg(src + gy * 256 + gx);
        dst[i] = v;
    }
}

__global__ __launch_bounds__(512) void k_main(
    const float* __restrict__ l1_w, const float* __restrict__ l1_b,
    const float* __restrict__ l2_w, const float* __restrict__ l2_b,
    const float* __restrict__ base_w, const float* __restrict__ bn_scale,
    const float* __restrict__ bn_bias, const float* __restrict__ final_w,
    const float* __restrict__ final_b, float* __restrict__ out) {
    // Regions for 32x16 tile: S=1: 18x34=612 @0; S=3: 22x38=836 @612;
    // S=5: 26x42=1092 @1448; S=7: 30x46=1380 @2540; total 3920
    __shared__ float sxt[3920];
    __shared__ float swB[4 * 16 * 14];   // per branch/channel: w1[4],b1,w2[8],b2
    __shared__ float sbase[64];
    __shared__ float sbnS[16], sbnB[16], sfw[16];

    int tid = threadIdx.x;
    for (int i = tid; i < 896; i += 512) {
        int e = i % 14;
        int rest = i / 14;
        int cc = rest % 16, br = rest / 16;
        float v;
        if (e < 4) { v = l1_w[(br * 16 + cc) * 4 + e]; if (e == 3) v *= 2.f; }
        else if (e == 4) v = l1_b[br * 16 + cc];
        else if (e < 13) v = l2_w[(br * 16 + cc) * 8 + (e - 5)];
        else v = l2_b[br * 16 + cc];
        swB[i] = v;
    }
    if (tid < 64) sbase[tid] = base_w[tid];
    if (tid < 16) { sbnS[tid] = bn_scale[tid]; sbnB[tid] = bn_bias[tid]; sfw[tid] = final_w[tid]; }

    int tx = tid & 31, ty = tid >> 5;     // ty 0..15
    int x0 = blockIdx.x * 32, y0 = blockIdx.y * 16;
    int b = blockIdx.z;
    float acc = __ldg(final_b);

#pragma unroll 1
    for (int c = 0; c < 16; c++) {
        __syncthreads();
        load_region<1>(sxt + 0,    g_xs + (size_t)((0 * BATCH + b) * 16 + c) * HW, y0, x0, tid);
        load_region<3>(sxt + 612,  g_xs + (size_t)((1 * BATCH + b) * 16 + c) * HW, y0, x0, tid);
        load_region<5>(sxt + 1448, g_xs + (size_t)((2 * BATCH + b) * 16 + c) * HW, y0, x0, tid);
        load_region<7>(sxt + 2540, g_xs + (size_t)((3 * BATCH + b) * 16 + c) * HW, y0, x0, tid);
        __syncthreads();

        float bv0 = branch_val<1, 34>(sxt + 0,    ty, tx, swB + (0 * 16 + c) * 14);
        float bv1 = branch_val<3, 38>(sxt + 612,  ty, tx, swB + (1 * 16 + c) * 14);
        float bv2 = branch_val<5, 42>(sxt + 1448, ty, tx, swB + (2 * 16 + c) * 14);
        float bv3 = branch_val<7, 46>(sxt + 2540, ty, tx, swB + (3 * 16 + c) * 14);

        // sort4 ascending
        ce(bv0, bv1); ce(bv2, bv3); ce(bv0, bv2); ce(bv1, bv3); ce(bv1, bv2);

        float y = bv0 * sbase[c * 4 + 0];
        y = fmaf(bv1, sbase[c * 4 + 1], y);
        y = fmaf(bv2, sbase[c * 4 + 2], y);
        y = fmaf(bv3, sbase[c * 4 + 3], y);
        float t = fmaf(y, sbnS[c], sbnB[c]);
        float si = __fdividef(t, 1.f + __expf(-t));          // SiLU (fast)
        acc = fmaf(si, sfw[c], acc);
    }
    out[(size_t)b * HW + (size_t)(y0 + ty) * 256 + (x0 + tx)] =
        __fdividef(1.f, 1.f + __expf(-acc));
}

// ---------------------------------------------------------------------------
extern "C" void kernel_launch(void* const* d_in, const int* in_sizes, int n_in,
                              void* d_out, int out_size) {
    (void)in_sizes; (void)n_in; (void)out_size;
    const float4* cen = (const float4*)d_in[0];
    // d_in[1] = mas (unused by the reference computation)
    const float* in_w = (const float*)d_in[2];
    const float* in_b = (const float*)d_in[3];

    k_inconv<<<512, 256>>>(cen, in_w, in_b);

    dim3 g2(8, 16, 8);   // W/32, H/16, B
    k_dw<<<g2, 256>>>((const float*)d_in[4],  (const float*)d_in[5],
                      (const float*)d_in[6],  (const float*)d_in[7],
                      (const float*)d_in[8],  (const float*)d_in[9],
                      (const float*)d_in[10], (const float*)d_in[11]);

    dim3 g3(8, 16, 8);   // W/32, H/16, B
    k_main<<<g3, 512>>>((const float*)d_in[12], (const float*)d_in[13],
                        (const float*)d_in[14], (const float*)d_in[15],
                        (const float*)d_in[16], (const float*)d_in[17],
                        (const float*)d_in[18], (const float*)d_in[19],
                        (const float*)d_in[20], (float*)d_out);
}

// round 4
// speedup vs baseline: 1.4423x; 1.4423x over previous
#include <cuda_runtime.h>

#define HH 256
#define WW 256
#define BATCH 8
#define HW 65536

// Scratch (allocation-free rule: __device__ globals)
__device__ float g_x[BATCH * 16 * HW];          // in_conv output  (33.5 MB)
__device__ float g_xs[4 * BATCH * 16 * HW];     // dwconv outputs  (134 MB)

// ---------------------------------------------------------------------------
// K1: 1x1 in_conv 64 -> 16, float2 (2 px / thread), deep K-unroll for MLP
// ---------------------------------------------------------------------------
__global__ __launch_bounds__(256, 3) void k_inconv(const float2* __restrict__ cen2,
                                                   const float* __restrict__ w,
                                                   const float* __restrict__ bias) {
    __shared__ float sw[1024];
    __shared__ float sb[16];
    for (int i = threadIdx.x; i < 1024; i += 256) sw[i] = w[i];
    if (threadIdx.x < 16) sb[threadIdx.x] = bias[threadIdx.x];
    __syncthreads();

    int idx = blockIdx.x * 256 + threadIdx.x;   // 0 .. 262143  (b, p2)
    int b = idx >> 15;
    int p2 = idx & 32767;
    const float2* cp = cen2 + (size_t)(b * 64) * 32768 + p2;

    float2 acc[16];
#pragma unroll
    for (int o = 0; o < 16; o++) { float v = sb[o]; acc[o] = make_float2(v, v); }

#pragma unroll 8
    for (int i = 0; i < 64; i++) {
        float2 v = __ldg(cp + (size_t)i * 32768);
#pragma unroll
        for (int o = 0; o < 16; o++) {
            float wv = sw[o * 64 + i];
            acc[o].x = fmaf(v.x, wv, acc[o].x);
            acc[o].y = fmaf(v.y, wv, acc[o].y);
        }
    }
    float2* xp = reinterpret_cast<float2*>(g_x) + (size_t)(b * 16) * 32768 + p2;
#pragma unroll
    for (int o = 0; o < 16; o++) xp[(size_t)o * 32768] = acc[o];
}

// ---------------------------------------------------------------------------
// K2: all 4 depthwise convs (s = 1,3,5,7), tile 32x16, 2 px per thread,
//     register-prefetch pipeline over channels.
// ---------------------------------------------------------------------------
template <int S>
__device__ __forceinline__ void dw2(const float* __restrict__ sx, int ty, int c0,
                                    const float* __restrict__ wk, float bias,
                                    float& o0, float& o1) {
    constexpr int P = S / 2;
    float a0 = bias, a1 = bias;
#pragma unroll
    for (int kh = 0; kh < S; kh++) {
        const float* row = sx + (ty + 3 - P + kh) * 39 + (c0 + 3 - P);
        float v[S + 1];
#pragma unroll
        for (int j = 0; j <= S; j++) v[j] = row[j];
#pragma unroll
        for (int kw = 0; kw < S; kw++) {
            float wv = wk[kh * S + kw];
            a0 = fmaf(wv, v[kw], a0);
            a1 = fmaf(wv, v[kw + 1], a1);
        }
    }
    o0 = a0; o1 = a1;
}

// 22x38 = 836 elements, 256 threads -> 4 per thread
__device__ __forceinline__ void dw_prefetch(float r[4], const float* __restrict__ src,
                                            int y0, int x0, int tid) {
#pragma unroll
    for (int j = 0; j < 4; j++) {
        int i = tid + j * 256;
        float v = 0.f;
        if (i < 836) {
            int rr = i / 38, cl = i % 38;
            int gy = y0 - 3 + rr, gx = x0 - 3 + cl;
            if ((unsigned)gy < 256u && (unsigned)gx < 256u)
                v = __ldg(src + gy * 256 + gx);
        }
        r[j] = v;
    }
}

__device__ __forceinline__ void dw_commit(const float r[4], float* __restrict__ sxt,
                                          int tid) {
#pragma unroll
    for (int j = 0; j < 4; j++) {
        int i = tid + j * 256;
        if (i < 836) sxt[(i / 38) * 39 + (i % 38)] = r[j];
    }
}

__global__ __launch_bounds__(256) void k_dw(
    const float* __restrict__ w1, const float* __restrict__ b1,
    const float* __restrict__ w3, const float* __restrict__ b3,
    const float* __restrict__ w5, const float* __restrict__ b5,
    const float* __restrict__ w7, const float* __restrict__ b7) {
    __shared__ float sdw[16 * 84];   // per channel: [w1(1), w3(9), w5(25), w7(49)]
    __shared__ float sdb[64];        // [c][branch]
    __shared__ float sxt[22 * 39];   // one channel tile + halo 3 (stride 39)

    int tid = threadIdx.x;
    for (int i = tid; i < 16;  i += 256) sdw[i * 84] = w1[i];
    for (int i = tid; i < 144; i += 256) sdw[(i / 9)  * 84 + 1  + (i % 9)]  = w3[i];
    for (int i = tid; i < 400; i += 256) sdw[(i / 25) * 84 + 10 + (i % 25)] = w5[i];
    for (int i = tid; i < 784; i += 256) sdw[(i / 49) * 84 + 35 + (i % 49)] = w7[i];
    if (tid < 16) {
        sdb[tid * 4 + 0] = b1[tid]; sdb[tid * 4 + 1] = b3[tid];
        sdb[tid * 4 + 2] = b5[tid]; sdb[tid * 4 + 3] = b7[tid];
    }

    int ty = tid >> 4;          // 0..15
    int c0 = (tid & 15) * 2;    // tile-local col (even)
    int y0 = blockIdx.y * 16, x0 = blockIdx.x * 32;
    int b = blockIdx.z;
    int h = y0 + ty, wc0 = x0 + c0;

    float rb[4];
    dw_prefetch(rb, g_x + (size_t)(b * 16 + 0) * HW, y0, x0, tid);

#pragma unroll 1
    for (int c = 0; c < 16; c++) {
        __syncthreads();                 // smem free from previous compute
        dw_commit(rb, sxt, tid);
        __syncthreads();
        if (c < 15)                      // loads for c+1 fly during compute
            dw_prefetch(rb, g_x + (size_t)(b * 16 + c + 1) * HW, y0, x0, tid);

        const float* wcp = sdw + c * 84;
        size_t pix = (size_t)h * 256 + wc0;
        float o0, o1;
        dw2<1>(sxt, ty, c0, wcp + 0,  sdb[c * 4 + 0], o0, o1);
        *reinterpret_cast<float2*>(g_xs + (size_t)((0 * BATCH + b) * 16 + c) * HW + pix) = make_float2(o0, o1);
        dw2<3>(sxt, ty, c0, wcp + 1,  sdb[c * 4 + 1], o0, o1);
        *reinterpret_cast<float2*>(g_xs + (size_t)((1 * BATCH + b) * 16 + c) * HW + pix) = make_float2(o0, o1);
        dw2<5>(sxt, ty, c0, wcp + 10, sdb[c * 4 + 2], o0, o1);
        *reinterpret_cast<float2*>(g_xs + (size_t)((2 * BATCH + b) * 16 + c) * HW + pix) = make_float2(o0, o1);
        dw2<7>(sxt, ty, c0, wcp + 35, sdb[c * 4 + 3], o0, o1);
        *reinterpret_cast<float2*>(g_xs + (size_t)((3 * BATCH + b) * 16 + c) * HW + pix) = make_float2(o0, o1);
    }
}

// ---------------------------------------------------------------------------
// K3: fused shifts + grouped mixes + sort8 + branch contraction + sort4 +
//     base conv + SiLU + final 1x1 + sigmoid.  Tile 32x16, 512 threads,
//     register-prefetch pipeline over channels.
// ---------------------------------------------------------------------------
__device__ __forceinline__ void ce(float& a, float& b) {
    float lo = fminf(a, b);
    float hi = fmaxf(a, b);
    a = lo; b = hi;
}

template <int S, int C>
__device__ __forceinline__ float branch_val(const float* __restrict__ sx, int ty,
                                            int tx, const float* __restrict__ wB) {
    const float* ctr = sx + (ty + S) * C + (tx + S);
    float xc = ctr[0];
    float T[8];
    T[0] = xc - ctr[-S * C - S];
    T[1] = xc - ctr[-S * C];
    T[2] = xc - ctr[-S * C + S];
    T[3] = xc - ctr[S];
    T[4] = xc - ctr[S * C + S];
    T[5] = xc - ctr[S * C];
    T[6] = xc - ctr[S * C - S];
    T[7] = xc - ctr[-S];
    float Sv[4];
#pragma unroll
    for (int k = 0; k < 4; k++) Sv[k] = T[k] + T[k + 4];

    float w10 = wB[0], w11 = wB[1], w12 = wB[2], w13x2 = wB[3], b1 = wB[4];
    // o_k and o_{k+4} share the S-terms -> 4 shared bases
    float base[4];
#pragma unroll
    for (int j = 0; j < 4; j++) {
        float o = fmaf(w10, Sv[(j + 1) & 3], b1);
        o = fmaf(w11, Sv[(j + 3) & 3], o);
        base[j] = fmaf(w12, Sv[(j + 2) & 3], o);
    }
    float v[8];
#pragma unroll
    for (int k = 0; k < 8; k++)
        v[k] = fmaf(w13x2, T[(k + 4) & 7], base[k & 3]) * T[k];  // wB[3] pre-doubled

    // Batcher odd-even mergesort, 8 elems, 19 CEs, ascending
    ce(v[0], v[1]); ce(v[2], v[3]); ce(v[0], v[2]); ce(v[1], v[3]); ce(v[1], v[2]);
    ce(v[4], v[5]); ce(v[6], v[7]); ce(v[4], v[6]); ce(v[5], v[7]); ce(v[5], v[6]);
    ce(v[0], v[4]); ce(v[1], v[5]); ce(v[2], v[6]); ce(v[3], v[7]);
    ce(v[2], v[4]); ce(v[3], v[5]);
    ce(v[1], v[2]); ce(v[3], v[4]); ce(v[5], v[6]);

    float r = wB[13];
#pragma unroll
    for (int j = 0; j < 8; j++) r = fmaf(v[j], wB[5 + j], r);
    return r;
}

template <int S, int NR>
__device__ __forceinline__ void m_prefetch(float r[NR], const float* __restrict__ src,
                                           int y0, int x0, int tid) {
    constexpr int R = 16 + 2 * S, C = 32 + 2 * S;
#pragma unroll
    for (int j = 0; j < NR; j++) {
        int i = tid + j * 512;
        float v = 0.f;
        if (i < R * C) {
            int rr = i / C, cl = i % C;
            int gy = y0 - S + rr, gx = x0 - S + cl;
            if ((unsigned)gy < 256u && (unsigned)gx < 256u)
                v = __ldg(src + gy * 256 + gx);
        }
        r[j] = v;
    }
}

template <int S, int NR>
__device__ __forceinline__ void m_commit(const float r[NR], float* __restrict__ dst,
                                         int tid) {
    constexpr int R = 16 + 2 * S, C = 32 + 2 * S;
#pragma unroll
    for (int j = 0; j < NR; j++) {
        int i = tid + j * 512;
        if (i < R * C) dst[i] = r[j];
    }
}

__global__ __launch_bounds__(512) void k_main(
    const float* __restrict__ l1_w, const float* __restrict__ l1_b,
    const float* __restrict__ l2_w, const float* __restrict__ l2_b,
    const float* __restrict__ base_w, const float* __restrict__ bn_scale,
    const float* __restrict__ bn_bias, const float* __restrict__ final_w,
    const float* __restrict__ final_b, float* __restrict__ out) {
    // Regions for 32x16 tile: S=1: 18x34=612 @0; S=3: 22x38=836 @612;
    // S=5: 26x42=1092 @1448; S=7: 30x46=1380 @2540; total 3920
    __shared__ float sxt[3920];
    __shared__ float swB[4 * 16 * 14];   // per branch/channel: w1[4],b1,w2[8],b2
    __shared__ float sbase[64];
    __shared__ float sbnS[16], sbnB[16], sfw[16];

    int tid = threadIdx.x;
    for (int i = tid; i < 896; i += 512) {
        int e = i % 14;
        int rest = i / 14;
        int cc = rest % 16, br = rest / 16;
        float v;
        if (e < 4) { v = l1_w[(br * 16 + cc) * 4 + e]; if (e == 3) v *= 2.f; }
        else if (e == 4) v = l1_b[br * 16 + cc];
        else if (e < 13) v = l2_w[(br * 16 + cc) * 8 + (e - 5)];
        else v = l2_b[br * 16 + cc];
        swB[i] = v;
    }
    if (tid < 64) sbase[tid] = base_w[tid];
    if (tid < 16) { sbnS[tid] = bn_scale[tid]; sbnB[tid] = bn_bias[tid]; sfw[tid] = final_w[tid]; }

    int tx = tid & 31, ty = tid >> 5;     // ty 0..15
    int x0 = blockIdx.x * 32, y0 = blockIdx.y * 16;
    int b = blockIdx.z;
    float acc = __ldg(final_b);

    const float* s1 = g_xs + (size_t)((0 * BATCH + b) * 16) * HW;
    const float* s3 = g_xs + (size_t)((1 * BATCH + b) * 16) * HW;
    const float* s5 = g_xs + (size_t)((2 * BATCH + b) * 16) * HW;
    const float* s7 = g_xs + (size_t)((3 * BATCH + b) * 16) * HW;

    float r1[2], r3[2], r5[3], r7[3];
    m_prefetch<1, 2>(r1, s1, y0, x0, tid);
    m_prefetch<3, 2>(r3, s3, y0, x0, tid);
    m_prefetch<5, 3>(r5, s5, y0, x0, tid);
    m_prefetch<7, 3>(r7, s7, y0, x0, tid);

#pragma unroll 1
    for (int c = 0; c < 16; c++) {
        __syncthreads();                 // previous compute done, smem free
        m_commit<1, 2>(r1, sxt + 0,    tid);
        m_commit<3, 2>(r3, sxt + 612,  tid);
        m_commit<5, 3>(r5, sxt + 1448, tid);
        m_commit<7, 3>(r7, sxt + 2540, tid);
        __syncthreads();
        if (c < 15) {                    // next channel's loads fly during compute
            size_t off = (size_t)(c + 1) * HW;
            m_prefetch<1, 2>(r1, s1 + off, y0, x0, tid);
            m_prefetch<3, 2>(r3, s3 + off, y0, x0, tid);
            m_prefetch<5, 3>(r5, s5 + off, y0, x0, tid);
            m_prefetch<7, 3>(r7, s7 + off, y0, x0, tid);
        }

        float bv0 = branch_val<1, 34>(sxt + 0,    ty, tx, swB + (0 * 16 + c) * 14);
        float bv1 = branch_val<3, 38>(sxt + 612,  ty, tx, swB + (1 * 16 + c) * 14);
        float bv2 = branch_val<5, 42>(sxt + 1448, ty, tx, swB + (2 * 16 + c) * 14);
        float bv3 = branch_val<7, 46>(sxt + 2540, ty, tx, swB + (3 * 16 + c) * 14);

        // sort4 ascending
        ce(bv0, bv1); ce(bv2, bv3); ce(bv0, bv2); ce(bv1, bv3); ce(bv1, bv2);

        float y = bv0 * sbase[c * 4 + 0];
        y = fmaf(bv1, sbase[c * 4 + 1], y);
        y = fmaf(bv2, sbase[c * 4 + 2], y);
        y = fmaf(bv3, sbase[c * 4 + 3], y);
        float t = fmaf(y, sbnS[c], sbnB[c]);
        float si = __fdividef(t, 1.f + __expf(-t));          // SiLU (fast)
        acc = fmaf(si, sfw[c], acc);
    }
    out[(size_t)b * HW + (size_t)(y0 + ty) * 256 + (x0 + tx)] =
        __fdividef(1.f, 1.f + __expf(-acc));
}

// ---------------------------------------------------------------------------
extern "C" void kernel_launch(void* const* d_in, const int* in_sizes, int n_in,
                              void* d_out, int out_size) {
    (void)in_sizes; (void)n_in; (void)out_size;
    const float2* cen = (const float2*)d_in[0];
    // d_in[1] = mas (unused by the reference computation)
    const float* in_w = (const float*)d_in[2];
    const float* in_b = (const float*)d_in[3];

    k_inconv<<<1024, 256>>>(cen, in_w, in_b);

    dim3 g2(8, 16, 8);   // W/32, H/16, B
    k_dw<<<g2, 256>>>((const float*)d_in[4],  (const float*)d_in[5],
                      (const float*)d_in[6],  (const float*)d_in[7],
                      (const float*)d_in[8],  (const float*)d_in[9],
                      (const float*)d_in[10], (const float*)d_in[11]);

    dim3 g3(8, 16, 8);   // W/32, H/16, B
    k_main<<<g3, 512>>>((const float*)d_in[12], (const float*)d_in[13],
                        (const float*)d_in[14], (const float*)d_in[15],
                        (const float*)d_in[16], (const float*)d_in[17],
                        (const float*)d_in[18], (const float*)d_in[19],
                        (const float*)d_in[20], (float*)d_out);
}